// round 14
// baseline (speedup 1.0000x reference)
#include <cuda_runtime.h>

// OTAM soft-DTW, exp-domain, 2-lane wavefront split + BULK-COPY staging.
// dists: [256, 64, 48, 48] f32 -> out: [256, 64] f32
//
// E = exp(-cum/lbda), lbda = 0.5:
//   E_cur[m] = w[m]*(E_prev[m-1] + E_cur[m-1] (+ E_prev[m] at m==1, m==49)),
//   w = exp(-2 d) = exp2(C*d).  Row 0 == general cell with E_prev == 0.
//   answer = -0.5*ln(E_final[49]).
//
// Compute identical to R13 (passed): lane pair (2p,2p+1), A computes
// m=1..24 of row t, B computes m=25..49 of row t-1; groups of 3 rows,
// ring of 3 slots. Staging replaced: per group, lane 0 issues 16
// cp.async.bulk copies (576 B contiguous per problem) completing on an
// mbarrier — bypasses the per-thread LDGSTS/L1tex path entirely.

#define LQ 48
#define MQ 48
#define PPW 16                                // problems per warp/CTA
#define PSTRIDE_B (LQ * MQ * 4)               // 9216 bytes per problem
#define GR 3                                  // rows per staging group
#define GRP_B (GR * MQ * 4)                   // 576 bytes per problem per group
#define NG 16                                 // groups (48 rows)
#define RING 3
#define PPAD_B 592                            // smem pitch per problem (16-al)
#define SLOT_B (PPW * PPAD_B)                 // 9472 bytes per slot
#define MBAR_B 64                             // 3 mbarriers + pad
#define SMEM_BYTES (MBAR_B + RING * SLOT_B)   // 28480 B

__device__ __forceinline__ float ex2f(float x) {
    float y; asm("ex2.approx.f32 %0, %1;" : "=f"(y) : "f"(x)); return y;
}
__device__ __forceinline__ float lg2f(float x) {
    float y; asm("lg2.approx.f32 %0, %1;" : "=f"(y) : "f"(x)); return y;
}
__device__ __forceinline__ void mbar_init(unsigned mbar, unsigned cnt) {
    asm volatile("mbarrier.init.shared.b64 [%0], %1;" :: "r"(mbar), "r"(cnt) : "memory");
}
__device__ __forceinline__ void mbar_expect_tx(unsigned mbar, unsigned bytes) {
    asm volatile("mbarrier.arrive.expect_tx.shared::cta.b64 _, [%0], %1;"
                 :: "r"(mbar), "r"(bytes) : "memory");
}
__device__ __forceinline__ void mbar_wait(unsigned mbar, unsigned phase) {
    asm volatile(
        "{\n\t.reg .pred P;\n"
        "WL_%=:\n\t"
        "mbarrier.try_wait.parity.shared::cta.b64 P, [%0], %1;\n\t"
        "@!P bra WL_%=;\n\t"
        "}\n" :: "r"(mbar), "r"(phase) : "memory");
}
__device__ __forceinline__ void bulk_cp(unsigned dst, const void* src,
                                        unsigned bytes, unsigned mbar) {
    asm volatile(
        "cp.async.bulk.shared::cta.global.mbarrier::complete_tx::bytes "
        "[%0], [%1], %2, [%3];"
        :: "r"(dst), "l"(src), "r"(bytes), "r"(mbar) : "memory");
}

extern __shared__ float4 smem4[];

// One DP wavefront step for this lane's 24 columns (verbatim from R13).
__device__ __forceinline__ void dp_step(const float4* __restrict__ rp,
                                        float* __restrict__ F,
                                        float& c, float& diag, int half) {
    float4 a0 = rp[0], a1 = rp[1], a2 = rp[2], a3 = rp[3], a4 = rp[4], a5 = rp[5];
#define CELLR(W, I) { float tt = F[I]; float wd = (W) * diag; \
                      c = fmaf((W), c, wd); diag = tt; F[I] = c; }
    {   // first cell: A has the m==1 edge include (E_prev[1] = old F[0]).
        float w0 = ex2f(a0.x * -2.885390081777927f);
        float tt = F[0];
        float ss = diag + c;
        if (!half) ss += tt;
        c = w0 * ss; diag = tt; F[0] = c;
    }
#define GRP(Q, B0) { float w0 = ex2f((Q).x * -2.885390081777927f); \
                     float w1 = ex2f((Q).y * -2.885390081777927f); \
                     float w2 = ex2f((Q).z * -2.885390081777927f); \
                     float w3 = ex2f((Q).w * -2.885390081777927f); \
                     CELLR(w0, (B0)) CELLR(w1, (B0)+1) CELLR(w2, (B0)+2) CELLR(w3, (B0)+3) }
    {   float w1 = ex2f(a0.y * -2.885390081777927f);
        float w2 = ex2f(a0.z * -2.885390081777927f);
        float w3 = ex2f(a0.w * -2.885390081777927f);
        CELLR(w1, 1) CELLR(w2, 2) CELLR(w3, 3) }
    GRP(a1, 4) GRP(a2, 8) GRP(a3, 12) GRP(a4, 16) GRP(a5, 20)
#undef GRP
#undef CELLR
    // B pad cell m==49: w = 1, edge include E_prev[49] (old F[24]).
    if (half) { float tt = F[24]; c = diag + c + tt; F[24] = c; }
}

__global__ void __launch_bounds__(32, 1)
otam_kernel(const float* __restrict__ dists, float* __restrict__ out) {
    const int lane = threadIdx.x;
    const int half = lane & 1;               // 0: A (cols 1..24), 1: B (25..49)
    const int p    = lane >> 1;              // problem within warp
    const int pbase = blockIdx.x * PPW;
    const char* gb = (const char*)dists + (size_t)pbase * PSTRIDE_B;

    const unsigned sbase = (unsigned)__cvta_generic_to_shared(smem4);
    const unsigned mb    = sbase;            // mbar[s] at mb + 8*s
    const unsigned dbase = sbase + MBAR_B;   // data slots
    const char* smem_c   = (const char*)smem4 + MBAR_B;

    // Init mbarriers, then prologue-load groups 0..2 into slots 0..2.
    if (lane == 0) {
#pragma unroll
        for (int s = 0; s < RING; s++) mbar_init(mb + 8u * s, 1u);
    }
    asm volatile("fence.proxy.async.shared::cta;" ::: "memory");
    __syncwarp();
    if (lane == 0) {
#pragma unroll
        for (int s = 0; s < RING; s++) {
            mbar_expect_tx(mb + 8u * s, PPW * GRP_B);
#pragma unroll
            for (int pp = 0; pp < PPW; pp++)
                bulk_cp(dbase + (unsigned)(s * SLOT_B + pp * PPAD_B),
                        gb + (size_t)pp * PSTRIDE_B + (size_t)s * GRP_B,
                        GRP_B, mb + 8u * s);
        }
    }

    float F[25];
#pragma unroll
    for (int i = 0; i < 25; i++) F[i] = 0.f;
    float c = 0.f, diag = 0.f;               // seam outputs (A -> B)
    float cin = 0.f, din = 0.f;              // B's received seam

    const int rboff = p * PPAD_B + half * 96;  // byte offset within a slot

#pragma unroll 1
    for (int g = 0; g < NG; g++) {
        const int u   = g / 3;               // usage index of slot s0
        const int s0  = g - 3 * u;           // slot of group g
        const int s2  = (s0 + 2 >= 3) ? s0 - 1 : s0 + 2;  // slot of group g-1
        // Wait for group g (slot s0, parity u&1). try_wait has acquire.
        mbar_wait(mb + 8u * s0, (unsigned)(u & 1));

#pragma unroll
        for (int rr = 0; rr < 3; rr++) {
            const int t = 3 * g + rr;
            // A reads group g row rr; B reads row t-1:
            //   rr==0 -> group g-1 row 2 (slot s2), else group g row rr-1.
            int sl = half ? ((rr == 0) ? s2 : s0) : s0;
            int rw = half ? ((rr == 0) ? 2 : rr - 1) : rr;
            const bool act = half ? (t >= 1) : true;
            if (act) {
                const float4* rp =
                    (const float4*)(smem_c + sl * SLOT_B + rboff + rw * 192);
                if (half == 0) { c = 1.f; diag = (t == 0) ? 0.f : 1.f; }
                else           { c = cin; diag = din; }
                dp_step(rp, F, c, diag, half);
            }
            // Seam handoff (consumed by B next step).
            float nc = __shfl_sync(0xffffffffu, c,    lane & ~1);
            float nd = __shfl_sync(0xffffffffu, diag, lane & ~1);
            if (half) { cin = nc; din = nd; }

            if (rr == 0) {
                // B just consumed the last row of group g-1 -> slot s2 free.
                __syncwarp();
                int G = g + 2;
                if (G >= RING && G < NG && lane == 0) {
                    unsigned mbs = mb + 8u * s2;
                    mbar_expect_tx(mbs, PPW * GRP_B);
#pragma unroll
                    for (int pp = 0; pp < PPW; pp++)
                        bulk_cp(dbase + (unsigned)(s2 * SLOT_B + pp * PPAD_B),
                                gb + (size_t)pp * PSTRIDE_B + (size_t)G * GRP_B,
                                GRP_B, mbs);
                }
            }
        }
    }

    // Epilogue step t=48: B computes row 47 (group 15 row 2, slot 15%3 == 0).
    if (half) {
        const float4* rp = (const float4*)(smem_c + 0 * SLOT_B + rboff + 2 * 192);
        c = cin; diag = din;
        dp_step(rp, F, c, diag, 1);
        out[pbase + p] = -0.34657359027997264f * lg2f(F[24]);
    }
}

extern "C" void kernel_launch(void* const* d_in, const int* in_sizes, int n_in,
                              void* d_out, int out_size) {
    const float* dists = (const float*)d_in[0];
    float* out = (float*)d_out;
    int B = in_sizes[0] / (LQ * MQ);         // 16384 problems
    int grid = B / PPW;                      // 1024 CTAs (1 warp each)

    cudaFuncSetAttribute(otam_kernel, cudaFuncAttributeMaxDynamicSharedMemorySize,
                         SMEM_BYTES);
    otam_kernel<<<grid, 32, SMEM_BYTES>>>(dists, out);
}

// round 15
// speedup vs baseline: 1.0115x; 1.0115x over previous
#include <cuda_runtime.h>

// OTAM soft-DTW, exp-domain, 2-lane split, DIRECT-LDG register pipeline.
// dists: [256, 64, 48, 48] f32 -> out: [256, 64] f32
//
// E = exp(-cum/lbda), lbda = 0.5:
//   E_cur[m] = w[m]*(E_prev[m-1] + E_cur[m-1] (+ E_prev[m] at m==1, m==49)),
//   w = exp(-2 d) = exp2(C*d).  Row 0 == general cell with E_prev == 0.
//   answer = -0.5*ln(E_final[49]).
//
// Lane pair (2p, 2p+1): even lane (A) computes m=1..24 of row t at step t,
// odd lane (B) computes m=25..49 of row t-2 at step t (2-row skew so both
// halves consume the same row parity -> uniform ping-pong buffers).
// Seam (E_cur[24], E_prev[24]) passes A->B through a 2-deep shuffle queue.
// No shared memory, no cp.async, no syncs: each lane streams its 96 B
// half-rows with LDG.128 into registers, prefetched 2 steps ahead.

#define LQ 48
#define MQ 48
#define PPW 16                               // problems per warp/CTA

__device__ __forceinline__ float ex2f(float x) {
    float y; asm("ex2.approx.f32 %0, %1;" : "=f"(y) : "f"(x)); return y;
}
__device__ __forceinline__ float lg2f(float x) {
    float y; asm("lg2.approx.f32 %0, %1;" : "=f"(y) : "f"(x)); return y;
}

// One DP step over this lane's 24 columns (structure verbatim from R13/R11,
// both passed). c/diag pre-initialized by caller.
__device__ __forceinline__ void dp_step(const float4* __restrict__ b,
                                        float* __restrict__ F,
                                        float& c, float& diag, int half) {
    float4 a0 = b[0], a1 = b[1], a2 = b[2], a3 = b[3], a4 = b[4], a5 = b[5];
#define CELLR(W, I) { float tt = F[I]; float wd = (W) * diag; \
                      c = fmaf((W), c, wd); diag = tt; F[I] = c; }
    {   // first cell: A has the m==1 edge include (E_prev[1] = old F[0]).
        float w0 = ex2f(a0.x * -2.885390081777927f);
        float tt = F[0];
        float ss = diag + c;
        if (!half) ss += tt;
        c = w0 * ss; diag = tt; F[0] = c;
    }
#define GRP4(Q, B0) { float w0 = ex2f((Q).x * -2.885390081777927f); \
                      float w1 = ex2f((Q).y * -2.885390081777927f); \
                      float w2 = ex2f((Q).z * -2.885390081777927f); \
                      float w3 = ex2f((Q).w * -2.885390081777927f); \
                      CELLR(w0, (B0)) CELLR(w1, (B0)+1) CELLR(w2, (B0)+2) CELLR(w3, (B0)+3) }
    {   float w1 = ex2f(a0.y * -2.885390081777927f);
        float w2 = ex2f(a0.z * -2.885390081777927f);
        float w3 = ex2f(a0.w * -2.885390081777927f);
        CELLR(w1, 1) CELLR(w2, 2) CELLR(w3, 3) }
    GRP4(a1, 4) GRP4(a2, 8) GRP4(a3, 12) GRP4(a4, 16) GRP4(a5, 20)
#undef GRP4
#undef CELLR
    // B pad cell m==49: w = 1, edge include E_prev[49] (old F[24]).
    if (half) { float tt = F[24]; c = diag + c + tt; F[24] = c; }
}

__global__ void __launch_bounds__(32, 1)
otam_kernel(const float* __restrict__ dists, float* __restrict__ out) {
    const int lane = threadIdx.x;
    const int half = lane & 1;               // 0: A (cols 1..24), 1: B (25..49)
    const int p    = lane >> 1;              // problem within warp
    const int pbase = blockIdx.x * PPW;

    // This lane's half-row stream: 96 B (6 float4) per row, rows 0..47.
    const float4* gp4 = (const float4*)(dists
                        + (size_t)(pbase + p) * (LQ * MQ) + half * 24);

    float F[25];
#pragma unroll
    for (int i = 0; i < 25; i++) F[i] = 0.f;
    float c = 0.f, diag = 0.f;               // A's seam outputs (post-row)
    float cin0 = 0.f, din0 = 0.f;            // seam queue: consume now
    float cin1 = 0.f, din1 = 0.f;            //             consume next

    // Ping-pong register buffers: row r lives in Bu[r&1].
    float4 Bu0[6], Bu1[6];
#pragma unroll
    for (int j = 0; j < 6; j++) Bu0[j] = gp4[j];            // row 0
#pragma unroll
    for (int j = 0; j < 6; j++) Bu1[j] = gp4[12 + j];       // row 1

#define BODY(T, BUF)                                                        \
    {                                                                       \
        const int ridx = (T) - 2 * half;     /* row this lane computes */   \
        const bool act = (ridx >= 0) && (ridx < LQ);                        \
        if (act) {                                                          \
            if (half == 0) { c = 1.f; diag = (ridx == 0) ? 0.f : 1.f; }     \
            else           { c = cin0; diag = din0; }                       \
            dp_step(BUF, F, c, diag, half);                                 \
        }                                                                   \
        /* seam handoff: B consumes A's row-r seam two steps later */       \
        float nc = __shfl_sync(0xffffffffu, c,    lane & ~1);               \
        float nd = __shfl_sync(0xffffffffu, diag, lane & ~1);               \
        if (half) { cin0 = cin1; din0 = din1; cin1 = nc; din1 = nd; }       \
        /* prefetch row ridx+2 into the buffer just consumed */             \
        const int lr = ridx + 2;                                            \
        if (lr >= 2 && lr < LQ) {                                           \
            const float4* rp = gp4 + lr * 12;                               \
            _Pragma("unroll")                                               \
            for (int j = 0; j < 6; j++) BUF[j] = rp[j];                     \
        }                                                                   \
    }

#pragma unroll 1
    for (int t = 0; t < LQ + 2; t += 2) {    // steps 0..49
        BODY(t,     Bu0)
        BODY(t + 1, Bu1)
    }
#undef BODY

    if (half)
        out[pbase + p] = -0.34657359027997264f * lg2f(F[24]);
}

extern "C" void kernel_launch(void* const* d_in, const int* in_sizes, int n_in,
                              void* d_out, int out_size) {
    const float* dists = (const float*)d_in[0];
    float* out = (float*)d_out;
    int B = in_sizes[0] / (LQ * MQ);         // 16384 problems
    int grid = B / PPW;                      // 1024 CTAs (1 warp each)

    otam_kernel<<<grid, 32>>>(dists, out);
}

// round 16
// speedup vs baseline: 1.0760x; 1.0638x over previous
#include <cuda_runtime.h>

// OTAM soft-DTW, exp-domain, 2-lane wavefront split (R11 base) + L2 prefetch.
// dists: [256, 64, 48, 48] f32 -> out: [256, 64] f32
//
// E = exp(-cum/lbda), lbda = 0.5:
//   E_cur[m] = w[m]*(E_prev[m-1] + E_cur[m-1] (+ E_prev[m] at m==1, m==49)),
//   w = exp(-2 d) = exp2(C*d).  Row 0 == general cell with E_prev == 0.
//   answer = -0.5*ln(E_final[49]).
//
// Lane pair (2p, 2p+1): even lane (A) computes m=1..24 of row t, odd lane (B)
// m=25..49 of row t-1 (1-row skew, seam via shuffle). 16 problems/warp,
// 1024 warps. 8-stage cp.async ring. NEW vs R11:
//   1. one warp-wide prefetch.global.L2 per step pulls row t+16 into L2,
//      so the cp.async closed loop completes from L2, not loaded DRAM;
//   2. smem reads are hoisted before the refill so requests go out earlier.

#define LQ 48
#define MQ 48
#define PPW 16                               // problems per warp/CTA
#define PSTRIDE (LQ * MQ)                    // 2304 floats per problem
#define PITCH4 13                            // float4 pitch (208 B), conflict-free
#define STAGE_F4 (PPW * PITCH4)              // 208 float4 = 3328 B per stage
#define STAGE_BYTES (STAGE_F4 * 16)
#define NS 8
#define PD 16                                // prefetch distance (rows)
#define SMEM_BYTES (NS * STAGE_BYTES)        // 26624 B per CTA

__device__ __forceinline__ float ex2f(float x) {
    float y; asm("ex2.approx.f32 %0, %1;" : "=f"(y) : "f"(x)); return y;
}
__device__ __forceinline__ float lg2f(float x) {
    float y; asm("lg2.approx.f32 %0, %1;" : "=f"(y) : "f"(x)); return y;
}
__device__ __forceinline__ void cp_async16_s(unsigned smem_dst, const void* gsrc) {
    asm volatile("cp.async.cg.shared.global [%0], [%1], 16;\n"
                 :: "r"(smem_dst), "l"(gsrc) : "memory");
}
__device__ __forceinline__ void prefetch_l2(const void* g) {
    asm volatile("prefetch.global.L2 [%0];" :: "l"(g));
}

extern __shared__ float4 smem4[];

// One DP wavefront step over this lane's 24 columns, on preloaded row data.
__device__ __forceinline__ void dp_step(float4 a0, float4 a1, float4 a2,
                                        float4 a3, float4 a4, float4 a5,
                                        float* __restrict__ F,
                                        float& c, float& diag, int half) {
#define CELLR(W, I) { float tt = F[I]; float wd = (W) * diag; \
                      c = fmaf((W), c, wd); diag = tt; F[I] = c; }
    {   // first cell: A has the m==1 edge include (E_prev[1] = old F[0]).
        float w0 = ex2f(a0.x * -2.885390081777927f);
        float tt = F[0];
        float ss = diag + c;
        if (!half) ss += tt;
        c = w0 * ss; diag = tt; F[0] = c;
    }
#define GRP4(Q, B0) { float w0 = ex2f((Q).x * -2.885390081777927f); \
                      float w1 = ex2f((Q).y * -2.885390081777927f); \
                      float w2 = ex2f((Q).z * -2.885390081777927f); \
                      float w3 = ex2f((Q).w * -2.885390081777927f); \
                      CELLR(w0, (B0)) CELLR(w1, (B0)+1) CELLR(w2, (B0)+2) CELLR(w3, (B0)+3) }
    {   float w1 = ex2f(a0.y * -2.885390081777927f);
        float w2 = ex2f(a0.z * -2.885390081777927f);
        float w3 = ex2f(a0.w * -2.885390081777927f);
        CELLR(w1, 1) CELLR(w2, 2) CELLR(w3, 3) }
    GRP4(a1, 4) GRP4(a2, 8) GRP4(a3, 12) GRP4(a4, 16) GRP4(a5, 20)
#undef GRP4
#undef CELLR
    // B pad cell m==49: w = 1, edge include E_prev[49] (old F[24]).
    if (half) { float tt = F[24]; c = diag + c + tt; F[24] = c; }
}

__global__ void __launch_bounds__(32, 1)
otam_kernel(const float* __restrict__ dists, float* __restrict__ out) {
    const int lane = threadIdx.x;
    const int half = lane & 1;               // 0: A (cols 1..24), 1: B (25..49)
    const int p    = lane >> 1;              // problem within warp
    const int pbase = blockIdx.x * PPW;
    const float* gbase = dists + (size_t)pbase * PSTRIDE;

    // Staging map (hoisted, as in R11): 192 chunks of 16 B per row, 6/lane.
    int sgo[6]; unsigned sso[6];
    const unsigned sbase = (unsigned)__cvta_generic_to_shared(smem4);
#pragma unroll
    for (int k = 0; k < 6; k++) {
        int ch = lane + k * 32;
        int pp = ch / 12;
        int j  = ch - pp * 12;
        sgo[k] = pp * PSTRIDE + j * 4;
        sso[k] = sbase + (unsigned)(pp * PITCH4 + j) * 16u;
    }

    // Per-lane L2-prefetch address: lane = 2*pp + i covers problem pp,
    // 128B line i of its 192B row segment (line 1 overlaps next row; harmless).
    const float* pfb = gbase + p * PSTRIDE + half * 32;

    // Prologue: rows 0..NS-1 into stages 0..NS-1.
#pragma unroll
    for (int s = 0; s < NS; s++) {
        const float* gr = gbase + s * MQ;
#pragma unroll
        for (int k = 0; k < 6; k++)
            cp_async16_s(sso[k] + (unsigned)(s * STAGE_BYTES), gr + sgo[k]);
        asm volatile("cp.async.commit_group;\n" ::: "memory");
    }

    float F[25];
#pragma unroll
    for (int i = 0; i < 25; i++) F[i] = 0.f;
    float c = 0.f, diag = 0.f;               // A's seam outputs
    float cin = 0.f, din = 0.f;              // B's received seam

    const int rbase = p * PITCH4 + half * 6; // float4 units within a stage
    int sA = 0;                              // stage holding row t

#pragma unroll 1
    for (int t = 0; t <= LQ; t++) {          // 49 wavefront steps
        asm volatile("cp.async.wait_group %0;\n" :: "n"(NS - 2) : "memory");
        __syncwarp();                        // cross-lane visibility

        int sB = sA + NS - 1; if (sB >= NS) sB -= NS;   // = (t-1) % NS
        const bool act = half ? (t >= 1) : (t < LQ);

        // Load this lane's row data FIRST (stage contents always valid smem;
        // values unused when !act).
        int st = half ? sB : sA;
        const float4* rp = smem4 + st * STAGE_F4 + rbase;
        float4 a0 = rp[0], a1 = rp[1], a2 = rp[2],
               a3 = rp[3], a4 = rp[4], a5 = rp[5];

        // All lanes have read stage sB -> refill it NOW, before computing.
        __syncwarp();
        if (t >= 1) {
            int row = t + NS - 1;
            if (row < LQ) {
                const float* gr = gbase + row * MQ;
                unsigned sb = (unsigned)(sB * STAGE_BYTES);
#pragma unroll
                for (int k = 0; k < 6; k++)
                    cp_async16_s(sso[k] + sb, gr + sgo[k]);
            }
            asm volatile("cp.async.commit_group;\n" ::: "memory");  // empty ok
        }

        // L2 prefetch: row t+PD (one warp-wide instruction, 32 x 128B lines).
        if (t + PD < LQ)
            prefetch_l2(pfb + (t + PD) * MQ);

        if (act) {
            if (half == 0) { c = 1.f; diag = ((t) == 0) ? 0.f : 1.f; }
            else           { c = cin; diag = din; }
            dp_step(a0, a1, a2, a3, a4, a5, F, c, diag, half);
        }

        // Seam handoff (B consumes next step).
        float nc = __shfl_sync(0xffffffffu, c,    lane & ~1);
        float nd = __shfl_sync(0xffffffffu, diag, lane & ~1);
        if (half) { cin = nc; din = nd; }

        sA++; if (sA == NS) sA = 0;
    }

    if (half)
        out[pbase + p] = -0.34657359027997264f * lg2f(F[24]);
}

extern "C" void kernel_launch(void* const* d_in, const int* in_sizes, int n_in,
                              void* d_out, int out_size) {
    const float* dists = (const float*)d_in[0];
    float* out = (float*)d_out;
    int B = in_sizes[0] / PSTRIDE;           // 16384 problems
    int grid = B / PPW;                      // 1024 CTAs (1 warp each)

    cudaFuncSetAttribute(otam_kernel, cudaFuncAttributeMaxDynamicSharedMemorySize,
                         SMEM_BYTES);
    otam_kernel<<<grid, 32, SMEM_BYTES>>>(dists, out);
}

// round 17
// speedup vs baseline: 1.2419x; 1.1542x over previous
#include <cuda_runtime.h>

// OTAM soft-DTW, exp-domain, 2-lane wavefront split (R11 compute verbatim),
// delayed-refill ring: ONE syncwarp per step, refill issued before compute.
// dists: [256, 64, 48, 48] f32 -> out: [256, 64] f32
//
// E = exp(-cum/lbda), lbda = 0.5:
//   E_cur[m] = w[m]*(E_prev[m-1] + E_cur[m-1] (+ E_prev[m] at m==1, m==49)),
//   w = exp(-2 d) = exp2(C*d).  Row 0 == general cell with E_prev == 0.
//   answer = -0.5*ln(E_final[49]).
//
// Lane pair (2p, 2p+1): even lane (A) computes m=1..24 of row t, odd lane (B)
// m=25..49 of row t-1 (seam via shuffle). 16 problems/warp, 1024 warps.
// Ring: row r lives in slot r%8. At step t (after the single top-of-step
// wait+syncwarp) we first refill slot (t-2)%8 with row t+6 — that slot was
// last read at step t-1, and the syncwarp just ordered those reads — then
// read and compute. Ledger: 8 prologue commits + 1/step from t=2 => row t is
// commit #(t+1), total before step-t wait = t+6 => wait_group 5 exactly
// guarantees rows <= t have landed.

#define LQ 48
#define MQ 48
#define PPW 16                               // problems per warp/CTA
#define PSTRIDE (LQ * MQ)                    // 2304 floats per problem
#define PITCH4 13                            // float4 pitch (208 B), conflict-free
#define STAGE_F4 (PPW * PITCH4)              // 208 float4 = 3328 B per stage
#define STAGE_BYTES (STAGE_F4 * 16)
#define NS 8
#define SMEM_BYTES (NS * STAGE_BYTES)        // 26624 B per CTA

__device__ __forceinline__ float ex2f(float x) {
    float y; asm("ex2.approx.f32 %0, %1;" : "=f"(y) : "f"(x)); return y;
}
__device__ __forceinline__ float lg2f(float x) {
    float y; asm("lg2.approx.f32 %0, %1;" : "=f"(y) : "f"(x)); return y;
}
__device__ __forceinline__ void cp_async16_s(unsigned smem_dst, const void* gsrc) {
    asm volatile("cp.async.cg.shared.global [%0], [%1], 16;\n"
                 :: "r"(smem_dst), "l"(gsrc) : "memory");
}

extern __shared__ float4 smem4[];

__global__ void __launch_bounds__(32, 1)
otam_kernel(const float* __restrict__ dists, float* __restrict__ out) {
    const int lane = threadIdx.x;
    const int half = lane & 1;               // 0: A (cols 1..24), 1: B (25..49)
    const int p    = lane >> 1;              // problem within warp
    const int pbase = blockIdx.x * PPW;
    const float* gbase = dists + (size_t)pbase * PSTRIDE;

    // Staging map (hoisted): 192 chunks of 16 B per row, 6 per lane.
    // chunk ch = lane + 32k -> problem pp = ch/12, segment j = ch%12.
    // Global side: contiguous 192 B per problem-row -> coalesced.
    int sgo[6]; unsigned sso[6];
    const unsigned sbase = (unsigned)__cvta_generic_to_shared(smem4);
#pragma unroll
    for (int k = 0; k < 6; k++) {
        int ch = lane + k * 32;
        int pp = ch / 12;
        int j  = ch - pp * 12;
        sgo[k] = pp * PSTRIDE + j * 4;
        sso[k] = sbase + (unsigned)(pp * PITCH4 + j) * 16u;
    }

    // Prologue: rows 0..7 -> slots 0..7 (8 commits).
#pragma unroll
    for (int s = 0; s < NS; s++) {
        const float* gr = gbase + s * MQ;
#pragma unroll
        for (int k = 0; k < 6; k++)
            cp_async16_s(sso[k] + (unsigned)(s * STAGE_BYTES), gr + sgo[k]);
        asm volatile("cp.async.commit_group;\n" ::: "memory");
    }

    float F[25];
#pragma unroll
    for (int i = 0; i < 25; i++) F[i] = 0.f;
    float c = 0.f, diag = 0.f;               // A's seam outputs
    float cin = 0.f, din = 0.f;              // B's received seam

    const int rbase = p * PITCH4 + half * 6; // float4 units within a stage

#pragma unroll 1
    for (int t = 0; t <= LQ; t++) {          // 49 wavefront steps
        // Single sync point per step: rows <= t landed, and all lanes' reads
        // from the previous step are ordered before this step's refill.
        asm volatile("cp.async.wait_group 5;\n" ::: "memory");
        __syncwarp();

        // Refill FIRST: slot (t-2)%8 (freed at step t-1) <- row t+6.
        if (t >= 2) {
            int row = t + 6;
            if (row < LQ) {
                const float* gr = gbase + row * MQ;
                unsigned sb = (unsigned)(((t - 2) & (NS - 1)) * STAGE_BYTES);
#pragma unroll
                for (int k = 0; k < 6; k++)
                    cp_async16_s(sso[k] + sb, gr + sgo[k]);
            }
            asm volatile("cp.async.commit_group;\n" ::: "memory");  // empty ok
        }

        // Read + compute (verbatim R11 cell structure).
        const int r = t - half;              // row this lane computes
        const bool act = (r >= 0) && (r < LQ);
        if (act) {
            const float4* rp = smem4 + (r & (NS - 1)) * STAGE_F4 + rbase;
            float4 a0 = rp[0], a1 = rp[1], a2 = rp[2],
                   a3 = rp[3], a4 = rp[4], a5 = rp[5];

            if (half == 0) { c = 1.f; diag = (r == 0) ? 0.f : 1.f; }
            else           { c = cin; diag = din; }

#define CELLR(W, I) { float tt = F[I]; float wd = (W) * diag; \
                      c = fmaf((W), c, wd); diag = tt; F[I] = c; }
            {   // first cell: A has the m==1 edge include (E_prev[1]=old F[0]).
                float w0 = ex2f(a0.x * -2.885390081777927f);
                float tt = F[0];
                float ss = diag + c;
                if (!half) ss += tt;
                c = w0 * ss; diag = tt; F[0] = c;
            }
#define GRP4(Q, B0) { float w0 = ex2f((Q).x * -2.885390081777927f); \
                      float w1 = ex2f((Q).y * -2.885390081777927f); \
                      float w2 = ex2f((Q).z * -2.885390081777927f); \
                      float w3 = ex2f((Q).w * -2.885390081777927f); \
                      CELLR(w0, (B0)) CELLR(w1, (B0)+1) CELLR(w2, (B0)+2) CELLR(w3, (B0)+3) }
            {   float w1 = ex2f(a0.y * -2.885390081777927f);
                float w2 = ex2f(a0.z * -2.885390081777927f);
                float w3 = ex2f(a0.w * -2.885390081777927f);
                CELLR(w1, 1) CELLR(w2, 2) CELLR(w3, 3) }
            GRP4(a1, 4) GRP4(a2, 8) GRP4(a3, 12) GRP4(a4, 16) GRP4(a5, 20)
#undef GRP4
#undef CELLR
            // B pad cell m==49: w = 1, edge include E_prev[49] (old F[24]).
            if (half) { float tt = F[24]; c = diag + c + tt; F[24] = c; }
        }

        // Seam handoff (B consumes at the next step).
        cin = __shfl_sync(0xffffffffu, c,    lane & ~1);
        din = __shfl_sync(0xffffffffu, diag, lane & ~1);
    }

    if (half)
        out[pbase + p] = -0.34657359027997264f * lg2f(F[24]);
}

extern "C" void kernel_launch(void* const* d_in, const int* in_sizes, int n_in,
                              void* d_out, int out_size) {
    const float* dists = (const float*)d_in[0];
    float* out = (float*)d_out;
    int B = in_sizes[0] / PSTRIDE;           // 16384 problems
    int grid = B / PPW;                      // 1024 CTAs (1 warp each)

    cudaFuncSetAttribute(otam_kernel, cudaFuncAttributeMaxDynamicSharedMemorySize,
                         SMEM_BYTES);
    otam_kernel<<<grid, 32, SMEM_BYTES>>>(dists, out);
}